// round 14
// baseline (speedup 1.0000x reference)
#include <cuda_runtime.h>
#include <cuda_fp16.h>
#include <cstdint>

#define HID 128
#define MAXN 50000
#define MAXE 640000

// ---------------- scratch (device globals; no allocation allowed) ----------------
__device__ __align__(256) __half g_zh[MAXN * HID];    // fp16 layer output (agg input)
__device__ __align__(256) __half g_xh[MAXN * HID];    // fp16 copy of x (layer 0)
__device__ __align__(256) float g_agg[MAXN * HID];    // BN(z)+sum relu(...) (GEMM1 input)
__device__ __align__(256) float g_t[MAXN * HID];      // post-GEMM1 pre-BN
__device__ __align__(256) float g_stats[8 * 2 * HID]; // per-layer [sum|sumsq] slots
__device__ int g_cnt[MAXN];
__device__ int g_cur[MAXN];
__device__ int g_rowptr[MAXN + 1];
__device__ __align__(16) int2 g_elist2[MAXE];         // {edge, src} pairs (dst-sorted)

// ---------------- f32x2 helpers ----------------
__device__ __forceinline__ unsigned long long pk2(float a) {
    unsigned long long r;
    asm("mov.b64 %0, {%1, %1};" : "=l"(r) : "f"(a));
    return r;
}
__device__ __forceinline__ void fma2(unsigned long long& d, unsigned long long a, unsigned long long b) {
    asm("fma.rn.f32x2 %0, %1, %2, %0;" : "+l"(d) : "l"(a), "l"(b));
}
__device__ __forceinline__ float2 upk(unsigned long long v) {
    float2 r;
    asm("mov.b64 {%0, %1}, %2;" : "=f"(r.x), "=f"(r.y) : "l"(v));
    return r;
}

// ================= x -> fp16 (once per call) =================
__global__ void xconv_kernel(const float* __restrict__ x, int total8) {
    int i = blockIdx.x * blockDim.x + threadIdx.x;
    if (i >= total8) return;
    const float4* p = (const float4*)x + (size_t)i * 2;
    float4 a = __ldg(p);
    float4 b = __ldg(p + 1);
    __half2 h0 = __floats2half2_rn(a.x, a.y);
    __half2 h1 = __floats2half2_rn(a.z, a.w);
    __half2 h2 = __floats2half2_rn(b.x, b.y);
    __half2 h3 = __floats2half2_rn(b.z, b.w);
    uint4 o;
    o.x = *(unsigned*)&h0; o.y = *(unsigned*)&h1;
    o.z = *(unsigned*)&h2; o.w = *(unsigned*)&h3;
    ((uint4*)g_xh)[i] = o;
}

// ================= CSR build =================
__global__ void hist_kernel(const int* __restrict__ dst, int E) {
    int i = blockIdx.x * blockDim.x + threadIdx.x;
    if (i < E) atomicAdd(&g_cnt[dst[i]], 1);
}

__global__ void __launch_bounds__(1024) scan_kernel(int N, int E) {
    __shared__ int part[1024];
    int tid = threadIdx.x;
    int chunk = (N + 1023) / 1024;
    int base = tid * chunk;
    int s = 0;
    for (int j = 0; j < chunk; j++) {
        int idx = base + j;
        if (idx < N) s += g_cnt[idx];
    }
    part[tid] = s;
    __syncthreads();
    for (int off = 1; off < 1024; off <<= 1) {
        int v = (tid >= off) ? part[tid - off] : 0;
        __syncthreads();
        part[tid] += v;
        __syncthreads();
    }
    int run = (tid == 0) ? 0 : part[tid - 1];
    for (int j = 0; j < chunk; j++) {
        int idx = base + j;
        if (idx < N) {
            g_rowptr[idx] = run;
            run += g_cnt[idx];
            g_cnt[idx] = 0;
            g_cur[idx] = 0;
        }
    }
    if (tid == 1023) g_rowptr[N] = E;
    g_stats[tid] = 0.f;
    g_stats[tid + 1024] = 0.f;
}

// scatter: store {edge, src} so agg's critical path skips the src gather
__global__ void scatter_kernel(const int* __restrict__ dst, const int* __restrict__ src, int E) {
    int i = blockIdx.x * blockDim.x + threadIdx.x;
    if (i < E) {
        int d = dst[i];
        int p = atomicAdd(&g_cur[d], 1);
        g_elist2[g_rowptr[d] + p] = make_int2(i, src[i]);
    }
}

// ================= aggregate: warp per node, fp16 z gather, fused src =================
template <bool BN>
__global__ void __launch_bounds__(256) agg_kernel(
    const __half* __restrict__ z, const float* __restrict__ ea,
    const float* __restrict__ stat_in,
    const float* __restrict__ gamma, const float* __restrict__ beta,
    float* __restrict__ agg, int N, float invN) {
    __shared__ float s_sc[HID], s_sh[HID];
    if (BN) {
        if (threadIdx.x < HID) {
            int c = threadIdx.x;
            float mu = stat_in[c] * invN;
            float var = stat_in[HID + c] * invN - mu * mu;
            float sv = gamma[c] * rsqrtf(var + 1e-5f);
            s_sc[c] = sv;
            s_sh[c] = beta[c] - sv * mu;
        }
        __syncthreads();
    }
    int warp = (blockIdx.x * blockDim.x + threadIdx.x) >> 5;
    int lane = threadIdx.x & 31;
    if (warp >= N) return;

    float4 sc, sh;
    if (BN) {
        sc = *(const float4*)&s_sc[lane * 4];
        sh = *(const float4*)&s_sh[lane * 4];
    }

    int idx = g_rowptr[warp];
    const int end = g_rowptr[warp + 1];

    // self term: BN(z[node])
    float4 acc;
    {
        uint2 raw = __ldg((const uint2*)(z + (size_t)warp * HID) + lane);
        float2 f0 = __half22float2(*(__half2*)&raw.x);
        float2 f1 = __half22float2(*(__half2*)&raw.y);
        acc = make_float4(f0.x, f0.y, f1.x, f1.y);
        if (BN) {
            acc.x = fmaf(sc.x, acc.x, sh.x);
            acc.y = fmaf(sc.y, acc.y, sh.y);
            acc.z = fmaf(sc.z, acc.z, sh.z);
            acc.w = fmaf(sc.w, acc.w, sh.w);
        }
    }

#define EDGE_BODY(E_, S_)                                                     \
    {                                                                         \
        uint2 raw = __ldg((const uint2*)(z + (size_t)(S_) * HID) + lane);     \
        float2 f0 = __half22float2(*(__half2*)&raw.x);                        \
        float2 f1 = __half22float2(*(__half2*)&raw.y);                        \
        float4 av = __ldcs((const float4*)(ea + (size_t)(E_) * HID) + lane);  \
        float zx = f0.x, zy = f0.y, zz = f1.x, zw = f1.y;                     \
        if (BN) {                                                             \
            zx = fmaf(sc.x, zx, sh.x); zy = fmaf(sc.y, zy, sh.y);             \
            zz = fmaf(sc.z, zz, sh.z); zw = fmaf(sc.w, zw, sh.w);             \
        }                                                                     \
        acc.x += fmaxf(zx + av.x, 0.f);                                       \
        acc.y += fmaxf(zy + av.y, 0.f);                                       \
        acc.z += fmaxf(zz + av.z, 0.f);                                       \
        acc.w += fmaxf(zw + av.w, 0.f);                                       \
    }

    for (; idx + 4 <= end; idx += 4) {
        // four naturally-aligned 8B uniform loads (int2 array => always aligned)
        int2 p0 = __ldg(g_elist2 + idx);
        int2 p1 = __ldg(g_elist2 + idx + 1);
        int2 p2 = __ldg(g_elist2 + idx + 2);
        int2 p3 = __ldg(g_elist2 + idx + 3);
        EDGE_BODY(p0.x, p0.y) EDGE_BODY(p1.x, p1.y)
        EDGE_BODY(p2.x, p2.y) EDGE_BODY(p3.x, p3.y)
    }
    for (; idx < end; idx++) {
        int2 p = __ldg(g_elist2 + idx);
        EDGE_BODY(p.x, p.y)
    }
#undef EDGE_BODY
    ((float4*)(agg + (size_t)warp * HID))[lane] = acc;  // every row written: no memset
}

// ================= fused GEMM (R4/R9 mapping: warp w rows w*8, lane cols lane*4) ====
static const int GEMM_SMEM = (HID * HID + 64 * 132 + 2 * HID) * 4;  // 100352 B

template <bool BN_IN, bool RELU_IN, bool RELU_OUT, bool STATS, bool WRITE_H>
__global__ void __launch_bounds__(256) gemm_kernel(
    const float* __restrict__ A,
    const float* __restrict__ stat_in, const float* __restrict__ gamma,
    const float* __restrict__ beta, float invN,
    const float* __restrict__ W, const float* __restrict__ bias,
    float* __restrict__ out, __half* __restrict__ out_h,
    float* __restrict__ stat_out, int M) {
    extern __shared__ float smem[];
    float* Ws = smem;                        // [128][128]
    float* As = smem + HID * HID;            // [64][132]
    float* s_sc = smem + HID * HID + 64 * 132;
    float* s_sh = s_sc + HID;

    const int tid = threadIdx.x;
    const int lane = tid & 31;
    const int wid = tid >> 5;
    const int row0 = blockIdx.x * 64;

    if (BN_IN && tid < HID) {
        float mu = stat_in[tid] * invN;
        float var = stat_in[HID + tid] * invN - mu * mu;
        float sv = gamma[tid] * rsqrtf(var + 1e-5f);
        s_sc[tid] = sv;
        s_sh[tid] = beta[tid] - sv * mu;
    }

    const float4* Wg = (const float4*)W;
    float4* Ws4 = (float4*)Ws;
#pragma unroll
    for (int i = 0; i < 16; i++) Ws4[tid + 256 * i] = __ldg(Wg + tid + 256 * i);
    __syncthreads();

    for (int i = tid; i < 64 * 32; i += 256) {
        int r = i >> 5, c4 = i & 31;
        int gr = row0 + r;
        float4 v = make_float4(0.f, 0.f, 0.f, 0.f);
        if (gr < M) {
            v = __ldg((const float4*)(A + (size_t)gr * HID) + c4);
            if (BN_IN) {
                float4 s4 = *(const float4*)&s_sc[c4 * 4];
                float4 h4 = *(const float4*)&s_sh[c4 * 4];
                v.x = fmaf(s4.x, v.x, h4.x);
                v.y = fmaf(s4.y, v.y, h4.y);
                v.z = fmaf(s4.z, v.z, h4.z);
                v.w = fmaf(s4.w, v.w, h4.w);
            }
            if (RELU_IN) {
                v.x = fmaxf(v.x, 0.f); v.y = fmaxf(v.y, 0.f);
                v.z = fmaxf(v.z, 0.f); v.w = fmaxf(v.w, 0.f);
            }
        }
        *(float4*)&As[r * 132 + c4 * 4] = v;
    }
    __syncthreads();

    unsigned long long acc[16];
#pragma unroll
    for (int i = 0; i < 16; i++) acc[i] = 0ull;

    const int arow = wid * 8;
#pragma unroll 2
    for (int kk = 0; kk < HID; kk += 4) {
        float ar[8][4];
#pragma unroll
        for (int r = 0; r < 8; r++)
            *(float4*)ar[r] = *(const float4*)&As[(arow + r) * 132 + kk];
#pragma unroll
        for (int j = 0; j < 4; j++) {
            ulonglong2 w = *(const ulonglong2*)&Ws[(kk + j) * HID + lane * 4];
#pragma unroll
            for (int r = 0; r < 8; r++) {
                unsigned long long pa = pk2(ar[r][j]);
                fma2(acc[r * 2 + 0], pa, w.x);
                fma2(acc[r * 2 + 1], pa, w.y);
            }
        }
    }

    float bb[4];
    *(float4*)bb = __ldg((const float4*)bias + lane);
    float csum[4], csq[4];
#pragma unroll
    for (int j = 0; j < 4; j++) { csum[j] = 0.f; csq[j] = 0.f; }

#pragma unroll
    for (int r = 0; r < 8; r++) {
        int gr = row0 + arow + r;
        if (gr < M) {
            float2 u0 = upk(acc[r * 2 + 0]);
            float2 u1 = upk(acc[r * 2 + 1]);
            float v[4] = {u0.x + bb[0], u0.y + bb[1], u1.x + bb[2], u1.y + bb[3]};
            if (RELU_OUT) {
#pragma unroll
                for (int j = 0; j < 4; j++) v[j] = fmaxf(v[j], 0.f);
            }
            if (WRITE_H) {
                __half2 h0 = __floats2half2_rn(v[0], v[1]);
                __half2 h1 = __floats2half2_rn(v[2], v[3]);
                uint2 o;
                o.x = *(unsigned*)&h0;
                o.y = *(unsigned*)&h1;
                *(uint2*)(out_h + (size_t)gr * HID + lane * 4) = o;
            } else {
                *(float4*)(out + (size_t)gr * HID + lane * 4) =
                    make_float4(v[0], v[1], v[2], v[3]);
            }
            if (STATS) {
#pragma unroll
                for (int j = 0; j < 4; j++) { csum[j] += v[j]; csq[j] += v[j] * v[j]; }
            }
        }
    }

    if (STATS) {
        float* red = As;  // reuse: 8 warps x 256 floats
        __syncthreads();
#pragma unroll
        for (int j = 0; j < 4; j++) {
            red[wid * 256 + lane * 4 + j] = csum[j];
            red[wid * 256 + 128 + lane * 4 + j] = csq[j];
        }
        __syncthreads();
#pragma unroll
        for (int s = 4; s > 0; s >>= 1) {
            if (wid < s) {
                for (int i = lane; i < 256; i += 32)
                    red[wid * 256 + i] += red[(wid + s) * 256 + i];
            }
            __syncthreads();
        }
        if (wid == 0) {
#pragma unroll
            for (int j = 0; j < 4; j++) {
                atomicAdd(&stat_out[lane * 4 + j], red[lane * 4 + j]);
                atomicAdd(&stat_out[HID + lane * 4 + j], red[128 + lane * 4 + j]);
            }
        }
    }
}

// ================= launcher =================
extern "C" void kernel_launch(void* const* d_in, const int* in_sizes, int n_in,
                              void* d_out, int out_size) {
    const float* x = (const float*)d_in[0];
    const int* ei = (const int*)d_in[1];   // int32 (JAX default, x64 disabled)
    const float* ea = (const float*)d_in[2];
    const float* W1 = (const float*)d_in[3];
    const float* b1 = (const float*)d_in[4];
    const float* g1 = (const float*)d_in[5];
    const float* be1 = (const float*)d_in[6];
    const float* W2 = (const float*)d_in[7];
    const float* b2 = (const float*)d_in[8];
    const float* bn_g = (const float*)d_in[9];
    const float* bn_b = (const float*)d_in[10];

    int M = in_sizes[0] / HID;
    int E = in_sizes[2] / HID;
    float* out = (float*)d_out;

    void *agg_p, *zh_p, *xh_p, *t_p, *stats_p;
    cudaGetSymbolAddress(&agg_p, g_agg);
    cudaGetSymbolAddress(&zh_p, g_zh);
    cudaGetSymbolAddress(&xh_p, g_xh);
    cudaGetSymbolAddress(&t_p, g_t);
    cudaGetSymbolAddress(&stats_p, g_stats);
    float* stats = (float*)stats_p;

    cudaFuncSetAttribute(gemm_kernel<false, false, false, true, false>,
                         cudaFuncAttributeMaxDynamicSharedMemorySize, GEMM_SMEM);
    cudaFuncSetAttribute(gemm_kernel<true, true, true, true, true>,
                         cudaFuncAttributeMaxDynamicSharedMemorySize, GEMM_SMEM);
    cudaFuncSetAttribute(gemm_kernel<true, true, true, false, false>,
                         cudaFuncAttributeMaxDynamicSharedMemorySize, GEMM_SMEM);

    const int* srcI = ei;
    const int* dstI = ei + E;
    int eb = (E + 255) / 256;
    int gb = (M + 63) / 64;
    int ab = (M * 32 + 255) / 256;  // warp per node
    int xcb = (M * HID / 8 + 255) / 256;
    float invN = 1.0f / (float)M;

    // x -> fp16 + CSR build (scan zeroes stats/cnt/cur for graph replays)
    xconv_kernel<<<xcb, 256>>>(x, M * HID / 8);
    hist_kernel<<<eb, 256>>>(dstI, E);
    scan_kernel<<<1, 1024>>>(M, E);
    scatter_kernel<<<eb, 256>>>(dstI, srcI, E);

    for (int i = 0; i < 4; i++) {
        const __half* zsrc = (i == 0) ? (const __half*)xh_p : (const __half*)zh_p;
        float* stat_t = stats + (size_t)(2 * i) * 2 * HID;
        float* stat_z = stats + (size_t)(2 * i + 1) * 2 * HID;
        float* stat_z_prev = stats + (size_t)(2 * i - 1) * 2 * HID;

        // aggregate includes self/residual term: GEMM1 input fully formed here
        if (i == 0)
            agg_kernel<false><<<ab, 256>>>(zsrc, ea, nullptr, nullptr, nullptr,
                                           (float*)agg_p, M, invN);
        else
            agg_kernel<true><<<ab, 256>>>(zsrc, ea, stat_z_prev,
                                          bn_g + (size_t)(i - 1) * HID,
                                          bn_b + (size_t)(i - 1) * HID,
                                          (float*)agg_p, M, invN);

        // GEMM1: raw stage of agg (no transform), fp32 out t, stats
        gemm_kernel<false, false, false, true, false><<<gb, 256, GEMM_SMEM>>>(
            (const float*)agg_p, nullptr, nullptr, nullptr, invN,
            W1 + (size_t)i * HID * HID, b1 + (size_t)i * HID,
            (float*)t_p, nullptr, stat_t, M);

        // GEMM2: BN(t)+ReLU in, ReLU out
        if (i < 3)
            gemm_kernel<true, true, true, true, true><<<gb, 256, GEMM_SMEM>>>(
                (const float*)t_p, stat_t,
                g1 + (size_t)i * HID, be1 + (size_t)i * HID, invN,
                W2 + (size_t)i * HID * HID, b2 + (size_t)i * HID,
                nullptr, (__half*)zh_p, stat_z, M);
        else
            gemm_kernel<true, true, true, false, false><<<gb, 256, GEMM_SMEM>>>(
                (const float*)t_p, stat_t,
                g1 + (size_t)i * HID, be1 + (size_t)i * HID, invN,
                W2 + (size_t)i * HID * HID, b2 + (size_t)i * HID,
                out, nullptr, nullptr, M);
    }
}

// round 15
// speedup vs baseline: 1.0402x; 1.0402x over previous
#include <cuda_runtime.h>
#include <cuda_fp16.h>
#include <cstdint>

#define HID 128
#define MAXN 50000
#define MAXE 640000

// ---------------- scratch (device globals; no allocation allowed) ----------------
__device__ __align__(256) __half g_zh[MAXN * HID];    // fp16 layer output (agg input)
__device__ __align__(256) __half g_xh[MAXN * HID];    // fp16 copy of x (layer 0)
__device__ __align__(256) float g_agg[MAXN * HID];    // BN(z)+sum relu(...) (GEMM1 input)
__device__ __align__(256) float g_t[MAXN * HID];      // post-GEMM1 pre-BN
__device__ __align__(256) float g_stats[8 * 2 * HID]; // per-layer [sum|sumsq] slots
__device__ int g_cnt[MAXN];
__device__ int g_cur[MAXN];
__device__ int g_rowptr[MAXN + 1];
__device__ int g_elist[MAXE];

// ---------------- f32x2 helpers ----------------
__device__ __forceinline__ unsigned long long pk2(float a) {
    unsigned long long r;
    asm("mov.b64 %0, {%1, %1};" : "=l"(r) : "f"(a));
    return r;
}
__device__ __forceinline__ void fma2(unsigned long long& d, unsigned long long a, unsigned long long b) {
    asm("fma.rn.f32x2 %0, %1, %2, %0;" : "+l"(d) : "l"(a), "l"(b));
}
__device__ __forceinline__ float2 upk(unsigned long long v) {
    float2 r;
    asm("mov.b64 {%0, %1}, %2;" : "=f"(r.x), "=f"(r.y) : "l"(v));
    return r;
}

// ================= x -> fp16 (once per call) =================
__global__ void xconv_kernel(const float* __restrict__ x, int total8) {
    int i = blockIdx.x * blockDim.x + threadIdx.x;  // one 8-elem chunk
    if (i >= total8) return;
    const float4* p = (const float4*)x + (size_t)i * 2;
    float4 a = __ldg(p);
    float4 b = __ldg(p + 1);
    __half2 h0 = __floats2half2_rn(a.x, a.y);
    __half2 h1 = __floats2half2_rn(a.z, a.w);
    __half2 h2 = __floats2half2_rn(b.x, b.y);
    __half2 h3 = __floats2half2_rn(b.z, b.w);
    uint4 o;
    o.x = *(unsigned*)&h0; o.y = *(unsigned*)&h1;
    o.z = *(unsigned*)&h2; o.w = *(unsigned*)&h3;
    ((uint4*)g_xh)[i] = o;
}

// ================= CSR build =================
__global__ void hist_kernel(const int* __restrict__ dst, int E) {
    int i = blockIdx.x * blockDim.x + threadIdx.x;
    if (i < E) atomicAdd(&g_cnt[dst[i]], 1);
}

__global__ void __launch_bounds__(1024) scan_kernel(int N, int E) {
    __shared__ int part[1024];
    int tid = threadIdx.x;
    int chunk = (N + 1023) / 1024;
    int base = tid * chunk;
    int s = 0;
    for (int j = 0; j < chunk; j++) {
        int idx = base + j;
        if (idx < N) s += g_cnt[idx];
    }
    part[tid] = s;
    __syncthreads();
    for (int off = 1; off < 1024; off <<= 1) {
        int v = (tid >= off) ? part[tid - off] : 0;
        __syncthreads();
        part[tid] += v;
        __syncthreads();
    }
    int run = (tid == 0) ? 0 : part[tid - 1];
    for (int j = 0; j < chunk; j++) {
        int idx = base + j;
        if (idx < N) {
            g_rowptr[idx] = run;
            run += g_cnt[idx];
            g_cnt[idx] = 0;
            g_cur[idx] = 0;
        }
    }
    if (tid == 1023) g_rowptr[N] = E;
    g_stats[tid] = 0.f;
    g_stats[tid + 1024] = 0.f;
}

__global__ void scatter_kernel(const int* __restrict__ dst, int E) {
    int i = blockIdx.x * blockDim.x + threadIdx.x;
    if (i < E) {
        int d = dst[i];
        int p = atomicAdd(&g_cur[d], 1);
        g_elist[g_rowptr[d] + p] = i;
    }
}

// ================= aggregate: warp per node, fp16 z gather =================
template <bool BN>
__global__ void __launch_bounds__(256) agg_kernel(
    const __half* __restrict__ z, const float* __restrict__ ea,
    const int* __restrict__ srcI, const float* __restrict__ stat_in,
    const float* __restrict__ gamma, const float* __restrict__ beta,
    float* __restrict__ agg, int N, float invN) {
    __shared__ float s_sc[HID], s_sh[HID];
    if (BN) {
        if (threadIdx.x < HID) {
            int c = threadIdx.x;
            float mu = stat_in[c] * invN;
            float var = stat_in[HID + c] * invN - mu * mu;
            float sv = gamma[c] * rsqrtf(var + 1e-5f);
            s_sc[c] = sv;
            s_sh[c] = beta[c] - sv * mu;
        }
        __syncthreads();
    }
    int warp = (blockIdx.x * blockDim.x + threadIdx.x) >> 5;
    int lane = threadIdx.x & 31;
    if (warp >= N) return;

    float4 sc, sh;
    if (BN) {
        sc = *(const float4*)&s_sc[lane * 4];
        sh = *(const float4*)&s_sh[lane * 4];
    }

    int idx = g_rowptr[warp];
    const int end = g_rowptr[warp + 1];

    // self term: BN(z[node])
    float4 acc;
    {
        uint2 raw = __ldg((const uint2*)(z + (size_t)warp * HID) + lane);
        float2 f0 = __half22float2(*(__half2*)&raw.x);
        float2 f1 = __half22float2(*(__half2*)&raw.y);
        acc = make_float4(f0.x, f0.y, f1.x, f1.y);
        if (BN) {
            acc.x = fmaf(sc.x, acc.x, sh.x);
            acc.y = fmaf(sc.y, acc.y, sh.y);
            acc.z = fmaf(sc.z, acc.z, sh.z);
            acc.w = fmaf(sc.w, acc.w, sh.w);
        }
    }

#define EDGE_BODY(E_, S_)                                                     \
    {                                                                         \
        uint2 raw = __ldg((const uint2*)(z + (size_t)(S_) * HID) + lane);     \
        float2 f0 = __half22float2(*(__half2*)&raw.x);                        \
        float2 f1 = __half22float2(*(__half2*)&raw.y);                        \
        float4 av = __ldcs((const float4*)(ea + (size_t)(E_) * HID) + lane);  \
        float zx = f0.x, zy = f0.y, zz = f1.x, zw = f1.y;                     \
        if (BN) {                                                             \
            zx = fmaf(sc.x, zx, sh.x); zy = fmaf(sc.y, zy, sh.y);             \
            zz = fmaf(sc.z, zz, sh.z); zw = fmaf(sc.w, zw, sh.w);             \
        }                                                                     \
        acc.x += fmaxf(zx + av.x, 0.f);                                       \
        acc.y += fmaxf(zy + av.y, 0.f);                                       \
        acc.z += fmaxf(zz + av.z, 0.f);                                       \
        acc.w += fmaxf(zw + av.w, 0.f);                                       \
    }

    for (; idx + 4 <= end; idx += 4) {
        int e0 = __ldg(g_elist + idx);
        int e1 = __ldg(g_elist + idx + 1);
        int e2 = __ldg(g_elist + idx + 2);
        int e3 = __ldg(g_elist + idx + 3);
        int s0 = __ldg(srcI + e0);
        int s1 = __ldg(srcI + e1);
        int s2 = __ldg(srcI + e2);
        int s3 = __ldg(srcI + e3);
        EDGE_BODY(e0, s0) EDGE_BODY(e1, s1) EDGE_BODY(e2, s2) EDGE_BODY(e3, s3)
    }
    for (; idx < end; idx++) {
        int e0 = __ldg(g_elist + idx);
        int s0 = __ldg(srcI + e0);
        EDGE_BODY(e0, s0)
    }
#undef EDGE_BODY
    ((float4*)(agg + (size_t)warp * HID))[lane] = acc;  // every row written: no memset
}

// ================= fused GEMM (R4/R9 mapping: warp w rows w*8, lane cols lane*4) ====
static const int GEMM_SMEM = (HID * HID + 64 * 132 + 2 * HID) * 4;  // 100352 B

template <bool BN_IN, bool RELU_IN, bool RELU_OUT, bool STATS, bool WRITE_H>
__global__ void __launch_bounds__(256) gemm_kernel(
    const float* __restrict__ A,
    const float* __restrict__ stat_in, const float* __restrict__ gamma,
    const float* __restrict__ beta, float invN,
    const float* __restrict__ W, const float* __restrict__ bias,
    float* __restrict__ out, __half* __restrict__ out_h,
    float* __restrict__ stat_out, int M) {
    extern __shared__ float smem[];
    float* Ws = smem;                        // [128][128]
    float* As = smem + HID * HID;            // [64][132]
    float* s_sc = smem + HID * HID + 64 * 132;
    float* s_sh = s_sc + HID;

    const int tid = threadIdx.x;
    const int lane = tid & 31;
    const int wid = tid >> 5;
    const int row0 = blockIdx.x * 64;

    if (BN_IN && tid < HID) {
        float mu = stat_in[tid] * invN;
        float var = stat_in[HID + tid] * invN - mu * mu;
        float sv = gamma[tid] * rsqrtf(var + 1e-5f);
        s_sc[tid] = sv;
        s_sh[tid] = beta[tid] - sv * mu;
    }

    const float4* Wg = (const float4*)W;
    float4* Ws4 = (float4*)Ws;
#pragma unroll
    for (int i = 0; i < 16; i++) Ws4[tid + 256 * i] = __ldg(Wg + tid + 256 * i);
    __syncthreads();

    for (int i = tid; i < 64 * 32; i += 256) {
        int r = i >> 5, c4 = i & 31;
        int gr = row0 + r;
        float4 v = make_float4(0.f, 0.f, 0.f, 0.f);
        if (gr < M) {
            v = __ldg((const float4*)(A + (size_t)gr * HID) + c4);
            if (BN_IN) {
                float4 s4 = *(const float4*)&s_sc[c4 * 4];
                float4 h4 = *(const float4*)&s_sh[c4 * 4];
                v.x = fmaf(s4.x, v.x, h4.x);
                v.y = fmaf(s4.y, v.y, h4.y);
                v.z = fmaf(s4.z, v.z, h4.z);
                v.w = fmaf(s4.w, v.w, h4.w);
            }
            if (RELU_IN) {
                v.x = fmaxf(v.x, 0.f); v.y = fmaxf(v.y, 0.f);
                v.z = fmaxf(v.z, 0.f); v.w = fmaxf(v.w, 0.f);
            }
        }
        *(float4*)&As[r * 132 + c4 * 4] = v;
    }
    __syncthreads();

    unsigned long long acc[16];
#pragma unroll
    for (int i = 0; i < 16; i++) acc[i] = 0ull;

    const int arow = wid * 8;
#pragma unroll 2
    for (int kk = 0; kk < HID; kk += 4) {
        float ar[8][4];
#pragma unroll
        for (int r = 0; r < 8; r++)
            *(float4*)ar[r] = *(const float4*)&As[(arow + r) * 132 + kk];
#pragma unroll
        for (int j = 0; j < 4; j++) {
            ulonglong2 w = *(const ulonglong2*)&Ws[(kk + j) * HID + lane * 4];
#pragma unroll
            for (int r = 0; r < 8; r++) {
                unsigned long long pa = pk2(ar[r][j]);
                fma2(acc[r * 2 + 0], pa, w.x);
                fma2(acc[r * 2 + 1], pa, w.y);
            }
        }
    }

    float bb[4];
    *(float4*)bb = __ldg((const float4*)bias + lane);
    float csum[4], csq[4];
#pragma unroll
    for (int j = 0; j < 4; j++) { csum[j] = 0.f; csq[j] = 0.f; }

#pragma unroll
    for (int r = 0; r < 8; r++) {
        int gr = row0 + arow + r;
        if (gr < M) {
            float2 u0 = upk(acc[r * 2 + 0]);
            float2 u1 = upk(acc[r * 2 + 1]);
            float v[4] = {u0.x + bb[0], u0.y + bb[1], u1.x + bb[2], u1.y + bb[3]};
            if (RELU_OUT) {
#pragma unroll
                for (int j = 0; j < 4; j++) v[j] = fmaxf(v[j], 0.f);
            }
            if (WRITE_H) {
                __half2 h0 = __floats2half2_rn(v[0], v[1]);
                __half2 h1 = __floats2half2_rn(v[2], v[3]);
                uint2 o;
                o.x = *(unsigned*)&h0;
                o.y = *(unsigned*)&h1;
                *(uint2*)(out_h + (size_t)gr * HID + lane * 4) = o;
            } else {
                *(float4*)(out + (size_t)gr * HID + lane * 4) =
                    make_float4(v[0], v[1], v[2], v[3]);
            }
            if (STATS) {
#pragma unroll
                for (int j = 0; j < 4; j++) { csum[j] += v[j]; csq[j] += v[j] * v[j]; }
            }
        }
    }

    if (STATS) {
        float* red = As;  // reuse: 8 warps x 256 floats
        __syncthreads();
#pragma unroll
        for (int j = 0; j < 4; j++) {
            red[wid * 256 + lane * 4 + j] = csum[j];
            red[wid * 256 + 128 + lane * 4 + j] = csq[j];
        }
        __syncthreads();
#pragma unroll
        for (int s = 4; s > 0; s >>= 1) {
            if (wid < s) {
                for (int i = lane; i < 256; i += 32)
                    red[wid * 256 + i] += red[(wid + s) * 256 + i];
            }
            __syncthreads();
        }
        if (wid == 0) {
#pragma unroll
            for (int j = 0; j < 4; j++) {
                atomicAdd(&stat_out[lane * 4 + j], red[lane * 4 + j]);
                atomicAdd(&stat_out[HID + lane * 4 + j], red[128 + lane * 4 + j]);
            }
        }
    }
}

// ================= launcher =================
extern "C" void kernel_launch(void* const* d_in, const int* in_sizes, int n_in,
                              void* d_out, int out_size) {
    const float* x = (const float*)d_in[0];
    const int* ei = (const int*)d_in[1];   // int32 (JAX default, x64 disabled)
    const float* ea = (const float*)d_in[2];
    const float* W1 = (const float*)d_in[3];
    const float* b1 = (const float*)d_in[4];
    const float* g1 = (const float*)d_in[5];
    const float* be1 = (const float*)d_in[6];
    const float* W2 = (const float*)d_in[7];
    const float* b2 = (const float*)d_in[8];
    const float* bn_g = (const float*)d_in[9];
    const float* bn_b = (const float*)d_in[10];

    int M = in_sizes[0] / HID;
    int E = in_sizes[2] / HID;
    float* out = (float*)d_out;

    void *agg_p, *zh_p, *xh_p, *t_p, *stats_p;
    cudaGetSymbolAddress(&agg_p, g_agg);
    cudaGetSymbolAddress(&zh_p, g_zh);
    cudaGetSymbolAddress(&xh_p, g_xh);
    cudaGetSymbolAddress(&t_p, g_t);
    cudaGetSymbolAddress(&stats_p, g_stats);
    float* stats = (float*)stats_p;

    cudaFuncSetAttribute(gemm_kernel<false, false, false, true, false>,
                         cudaFuncAttributeMaxDynamicSharedMemorySize, GEMM_SMEM);
    cudaFuncSetAttribute(gemm_kernel<true, true, true, true, true>,
                         cudaFuncAttributeMaxDynamicSharedMemorySize, GEMM_SMEM);
    cudaFuncSetAttribute(gemm_kernel<true, true, true, false, false>,
                         cudaFuncAttributeMaxDynamicSharedMemorySize, GEMM_SMEM);

    const int* srcI = ei;
    const int* dstI = ei + E;
    int eb = (E + 255) / 256;
    int gb = (M + 63) / 64;
    int ab = (M * 32 + 255) / 256;  // warp per node
    int xcb = (M * HID / 8 + 255) / 256;
    float invN = 1.0f / (float)M;

    // x -> fp16 + CSR build (scan zeroes stats/cnt/cur for graph replays)
    xconv_kernel<<<xcb, 256>>>(x, M * HID / 8);
    hist_kernel<<<eb, 256>>>(dstI, E);
    scan_kernel<<<1, 1024>>>(M, E);
    scatter_kernel<<<eb, 256>>>(dstI, E);

    for (int i = 0; i < 4; i++) {
        const __half* zsrc = (i == 0) ? (const __half*)xh_p : (const __half*)zh_p;
        float* stat_t = stats + (size_t)(2 * i) * 2 * HID;
        float* stat_z = stats + (size_t)(2 * i + 1) * 2 * HID;
        float* stat_z_prev = stats + (size_t)(2 * i - 1) * 2 * HID;

        // aggregate includes self/residual term: GEMM1 input fully formed here
        if (i == 0)
            agg_kernel<false><<<ab, 256>>>(zsrc, ea, srcI, nullptr, nullptr, nullptr,
                                           (float*)agg_p, M, invN);
        else
            agg_kernel<true><<<ab, 256>>>(zsrc, ea, srcI, stat_z_prev,
                                          bn_g + (size_t)(i - 1) * HID,
                                          bn_b + (size_t)(i - 1) * HID,
                                          (float*)agg_p, M, invN);

        // GEMM1: raw stage of agg (no transform), fp32 out t, stats
        gemm_kernel<false, false, false, true, false><<<gb, 256, GEMM_SMEM>>>(
            (const float*)agg_p, nullptr, nullptr, nullptr, invN,
            W1 + (size_t)i * HID * HID, b1 + (size_t)i * HID,
            (float*)t_p, nullptr, stat_t, M);

        // GEMM2: BN(t)+ReLU in, ReLU out
        if (i < 3)
            gemm_kernel<true, true, true, true, true><<<gb, 256, GEMM_SMEM>>>(
                (const float*)t_p, stat_t,
                g1 + (size_t)i * HID, be1 + (size_t)i * HID, invN,
                W2 + (size_t)i * HID * HID, b2 + (size_t)i * HID,
                nullptr, (__half*)zh_p, stat_z, M);
        else
            gemm_kernel<true, true, true, false, false><<<gb, 256, GEMM_SMEM>>>(
                (const float*)t_p, stat_t,
                g1 + (size_t)i * HID, be1 + (size_t)i * HID, invN,
                W2 + (size_t)i * HID * HID, b2 + (size_t)i * HID,
                out, nullptr, nullptr, M);
    }
}

// round 16
// speedup vs baseline: 1.0450x; 1.0046x over previous
#include <cuda_runtime.h>
#include <cuda_fp16.h>
#include <cstdint>

#define HID 128
#define MAXN 50000
#define MAXE 640000

// ---------------- scratch (device globals; no allocation allowed) ----------------
__device__ __align__(256) __half g_zh[MAXN * HID];    // fp16 layer output (agg input)
__device__ __align__(256) __half g_xh[MAXN * HID];    // fp16 copy of x (layer 0)
__device__ __align__(256) float g_agg[MAXN * HID];    // BN(z)+sum relu(...) (GEMM1 input)
__device__ __align__(256) float g_t[MAXN * HID];      // post-GEMM1 pre-BN
__device__ __align__(256) float g_stats[8 * 2 * HID]; // per-layer [sum|sumsq] slots
__device__ int g_cnt[MAXN];
__device__ int g_cur[MAXN];
__device__ int g_rowptr[MAXN + 1];
__device__ int g_elist[MAXE];

// ---------------- f32x2 helpers ----------------
__device__ __forceinline__ unsigned long long pk2(float a) {
    unsigned long long r;
    asm("mov.b64 %0, {%1, %1};" : "=l"(r) : "f"(a));
    return r;
}
__device__ __forceinline__ void fma2(unsigned long long& d, unsigned long long a, unsigned long long b) {
    asm("fma.rn.f32x2 %0, %1, %2, %0;" : "+l"(d) : "l"(a), "l"(b));
}
__device__ __forceinline__ float2 upk(unsigned long long v) {
    float2 r;
    asm("mov.b64 {%0, %1}, %2;" : "=f"(r.x), "=f"(r.y) : "l"(v));
    return r;
}

// ================= x -> fp16 (once per call) =================
__global__ void xconv_kernel(const float* __restrict__ x, int total8) {
    int i = blockIdx.x * blockDim.x + threadIdx.x;  // one 8-elem chunk
    if (i >= total8) return;
    const float4* p = (const float4*)x + (size_t)i * 2;
    float4 a = __ldg(p);
    float4 b = __ldg(p + 1);
    __half2 h0 = __floats2half2_rn(a.x, a.y);
    __half2 h1 = __floats2half2_rn(a.z, a.w);
    __half2 h2 = __floats2half2_rn(b.x, b.y);
    __half2 h3 = __floats2half2_rn(b.z, b.w);
    uint4 o;
    o.x = *(unsigned*)&h0; o.y = *(unsigned*)&h1;
    o.z = *(unsigned*)&h2; o.w = *(unsigned*)&h3;
    ((uint4*)g_xh)[i] = o;
}

// ================= CSR build =================
__global__ void hist_kernel(const int* __restrict__ dst, int E) {
    int i = blockIdx.x * blockDim.x + threadIdx.x;
    if (i < E) atomicAdd(&g_cnt[dst[i]], 1);
}

__global__ void __launch_bounds__(1024) scan_kernel(int N, int E) {
    __shared__ int part[1024];
    int tid = threadIdx.x;
    int chunk = (N + 1023) / 1024;
    int base = tid * chunk;
    int s = 0;
    for (int j = 0; j < chunk; j++) {
        int idx = base + j;
        if (idx < N) s += g_cnt[idx];
    }
    part[tid] = s;
    __syncthreads();
    for (int off = 1; off < 1024; off <<= 1) {
        int v = (tid >= off) ? part[tid - off] : 0;
        __syncthreads();
        part[tid] += v;
        __syncthreads();
    }
    int run = (tid == 0) ? 0 : part[tid - 1];
    for (int j = 0; j < chunk; j++) {
        int idx = base + j;
        if (idx < N) {
            g_rowptr[idx] = run;
            run += g_cnt[idx];
            g_cnt[idx] = 0;
            g_cur[idx] = 0;
        }
    }
    if (tid == 1023) g_rowptr[N] = E;
    g_stats[tid] = 0.f;
    g_stats[tid + 1024] = 0.f;
}

__global__ void scatter_kernel(const int* __restrict__ dst, int E) {
    int i = blockIdx.x * blockDim.x + threadIdx.x;
    if (i < E) {
        int d = dst[i];
        int p = atomicAdd(&g_cur[d], 1);
        g_elist[g_rowptr[d] + p] = i;
    }
}

// ================= aggregate: warp per node, fp16 z gather =================
template <bool BN>
__global__ void __launch_bounds__(256) agg_kernel(
    const __half* __restrict__ z, const float* __restrict__ ea,
    const int* __restrict__ srcI, const float* __restrict__ stat_in,
    const float* __restrict__ gamma, const float* __restrict__ beta,
    float* __restrict__ agg, int N, float invN) {
    __shared__ float s_sc[HID], s_sh[HID];
    if (BN) {
        if (threadIdx.x < HID) {
            int c = threadIdx.x;
            float mu = stat_in[c] * invN;
            float var = stat_in[HID + c] * invN - mu * mu;
            float sv = gamma[c] * rsqrtf(var + 1e-5f);
            s_sc[c] = sv;
            s_sh[c] = beta[c] - sv * mu;
        }
        __syncthreads();
    }
    int warp = (blockIdx.x * blockDim.x + threadIdx.x) >> 5;
    int lane = threadIdx.x & 31;
    if (warp >= N) return;

    float4 sc, sh;
    if (BN) {
        sc = *(const float4*)&s_sc[lane * 4];
        sh = *(const float4*)&s_sh[lane * 4];
    }

    int idx = g_rowptr[warp];
    const int end = g_rowptr[warp + 1];

    // self term: BN(z[node])
    float4 acc;
    {
        uint2 raw = __ldg((const uint2*)(z + (size_t)warp * HID) + lane);
        float2 f0 = __half22float2(*(__half2*)&raw.x);
        float2 f1 = __half22float2(*(__half2*)&raw.y);
        acc = make_float4(f0.x, f0.y, f1.x, f1.y);
        if (BN) {
            acc.x = fmaf(sc.x, acc.x, sh.x);
            acc.y = fmaf(sc.y, acc.y, sh.y);
            acc.z = fmaf(sc.z, acc.z, sh.z);
            acc.w = fmaf(sc.w, acc.w, sh.w);
        }
    }

#define EDGE_BODY(E_, S_)                                                     \
    {                                                                         \
        uint2 raw = __ldg((const uint2*)(z + (size_t)(S_) * HID) + lane);     \
        float2 f0 = __half22float2(*(__half2*)&raw.x);                        \
        float2 f1 = __half22float2(*(__half2*)&raw.y);                        \
        float4 av = __ldcs((const float4*)(ea + (size_t)(E_) * HID) + lane);  \
        float zx = f0.x, zy = f0.y, zz = f1.x, zw = f1.y;                     \
        if (BN) {                                                             \
            zx = fmaf(sc.x, zx, sh.x); zy = fmaf(sc.y, zy, sh.y);             \
            zz = fmaf(sc.z, zz, sh.z); zw = fmaf(sc.w, zw, sh.w);             \
        }                                                                     \
        acc.x += fmaxf(zx + av.x, 0.f);                                       \
        acc.y += fmaxf(zy + av.y, 0.f);                                       \
        acc.z += fmaxf(zz + av.z, 0.f);                                       \
        acc.w += fmaxf(zw + av.w, 0.f);                                       \
    }

    for (; idx + 4 <= end; idx += 4) {
        int e0 = __ldg(g_elist + idx);
        int e1 = __ldg(g_elist + idx + 1);
        int e2 = __ldg(g_elist + idx + 2);
        int e3 = __ldg(g_elist + idx + 3);
        int s0 = __ldg(srcI + e0);
        int s1 = __ldg(srcI + e1);
        int s2 = __ldg(srcI + e2);
        int s3 = __ldg(srcI + e3);
        EDGE_BODY(e0, s0) EDGE_BODY(e1, s1) EDGE_BODY(e2, s2) EDGE_BODY(e3, s3)
    }
    for (; idx < end; idx++) {
        int e0 = __ldg(g_elist + idx);
        int s0 = __ldg(srcI + e0);
        EDGE_BODY(e0, s0)
    }
#undef EDGE_BODY
    ((float4*)(agg + (size_t)warp * HID))[lane] = acc;  // every row written: no memset
}

// ================= fused GEMM: barrier-free staging (BN inline from global) =========
static const int GEMM_SMEM = (HID * HID + 64 * 132) * 4;  // 99328 B

template <bool BN_IN, bool RELU_IN, bool RELU_OUT, bool STATS, bool WRITE_H>
__global__ void __launch_bounds__(256) gemm_kernel(
    const float* __restrict__ A,
    const float* __restrict__ stat_in, const float* __restrict__ gamma,
    const float* __restrict__ beta, float invN,
    const float* __restrict__ W, const float* __restrict__ bias,
    float* __restrict__ out, __half* __restrict__ out_h,
    float* __restrict__ stat_out, int M) {
    extern __shared__ float smem[];
    float* Ws = smem;              // [128][128]
    float* As = smem + HID * HID;  // [64][132]

    const int tid = threadIdx.x;
    const int lane = tid & 31;
    const int wid = tid >> 5;
    const int row0 = blockIdx.x * 64;

    // stage W (no barrier needed before A-stage: independent streams)
    const float4* Wg = (const float4*)W;
    float4* Ws4 = (float4*)Ws;
#pragma unroll
    for (int i = 0; i < 16; i++) Ws4[tid + 256 * i] = __ldg(Wg + tid + 256 * i);

    // stage A with BN transform computed inline from globals (L1-resident broadcasts)
    for (int i = tid; i < 64 * 32; i += 256) {
        int r = i >> 5, c4 = i & 31;
        int gr = row0 + r;
        float4 v = make_float4(0.f, 0.f, 0.f, 0.f);
        if (gr < M) {
            v = __ldg((const float4*)(A + (size_t)gr * HID) + c4);
            if (BN_IN) {
                float4 su = __ldg((const float4*)stat_in + c4);
                float4 sq = __ldg((const float4*)(stat_in + HID) + c4);
                float4 gm = __ldg((const float4*)gamma + c4);
                float4 bt = __ldg((const float4*)beta + c4);
                float mx = su.x * invN, my = su.y * invN, mz = su.z * invN, mw = su.w * invN;
                float s0 = gm.x * rsqrtf(sq.x * invN - mx * mx + 1e-5f);
                float s1 = gm.y * rsqrtf(sq.y * invN - my * my + 1e-5f);
                float s2 = gm.z * rsqrtf(sq.z * invN - mz * mz + 1e-5f);
                float s3 = gm.w * rsqrtf(sq.w * invN - mw * mw + 1e-5f);
                v.x = fmaf(s0, v.x, bt.x - s0 * mx);
                v.y = fmaf(s1, v.y, bt.y - s1 * my);
                v.z = fmaf(s2, v.z, bt.z - s2 * mz);
                v.w = fmaf(s3, v.w, bt.w - s3 * mw);
            }
            if (RELU_IN) {
                v.x = fmaxf(v.x, 0.f); v.y = fmaxf(v.y, 0.f);
                v.z = fmaxf(v.z, 0.f); v.w = fmaxf(v.w, 0.f);
            }
        }
        *(float4*)&As[r * 132 + c4 * 4] = v;
    }
    __syncthreads();  // single barrier: both stages drained

    unsigned long long acc[16];
#pragma unroll
    for (int i = 0; i < 16; i++) acc[i] = 0ull;

    const int arow = wid * 8;
#pragma unroll 2
    for (int kk = 0; kk < HID; kk += 4) {
        float ar[8][4];
#pragma unroll
        for (int r = 0; r < 8; r++)
            *(float4*)ar[r] = *(const float4*)&As[(arow + r) * 132 + kk];
#pragma unroll
        for (int j = 0; j < 4; j++) {
            ulonglong2 w = *(const ulonglong2*)&Ws[(kk + j) * HID + lane * 4];
#pragma unroll
            for (int r = 0; r < 8; r++) {
                unsigned long long pa = pk2(ar[r][j]);
                fma2(acc[r * 2 + 0], pa, w.x);
                fma2(acc[r * 2 + 1], pa, w.y);
            }
        }
    }

    float bb[4];
    *(float4*)bb = __ldg((const float4*)bias + lane);
    float csum[4], csq[4];
#pragma unroll
    for (int j = 0; j < 4; j++) { csum[j] = 0.f; csq[j] = 0.f; }

#pragma unroll
    for (int r = 0; r < 8; r++) {
        int gr = row0 + arow + r;
        if (gr < M) {
            float2 u0 = upk(acc[r * 2 + 0]);
            float2 u1 = upk(acc[r * 2 + 1]);
            float v[4] = {u0.x + bb[0], u0.y + bb[1], u1.x + bb[2], u1.y + bb[3]};
            if (RELU_OUT) {
#pragma unroll
                for (int j = 0; j < 4; j++) v[j] = fmaxf(v[j], 0.f);
            }
            if (WRITE_H) {
                __half2 h0 = __floats2half2_rn(v[0], v[1]);
                __half2 h1 = __floats2half2_rn(v[2], v[3]);
                uint2 o;
                o.x = *(unsigned*)&h0;
                o.y = *(unsigned*)&h1;
                *(uint2*)(out_h + (size_t)gr * HID + lane * 4) = o;
            } else {
                *(float4*)(out + (size_t)gr * HID + lane * 4) =
                    make_float4(v[0], v[1], v[2], v[3]);
            }
            if (STATS) {
#pragma unroll
                for (int j = 0; j < 4; j++) { csum[j] += v[j]; csq[j] += v[j] * v[j]; }
            }
        }
    }

    if (STATS) {
        float* red = As;  // reuse: 8 warps x 256 floats
        __syncthreads();
#pragma unroll
        for (int j = 0; j < 4; j++) {
            red[wid * 256 + lane * 4 + j] = csum[j];
            red[wid * 256 + 128 + lane * 4 + j] = csq[j];
        }
        __syncthreads();
#pragma unroll
        for (int s = 4; s > 0; s >>= 1) {
            if (wid < s) {
                for (int i = lane; i < 256; i += 32)
                    red[wid * 256 + i] += red[(wid + s) * 256 + i];
            }
            __syncthreads();
        }
        if (wid == 0) {
#pragma unroll
            for (int j = 0; j < 4; j++) {
                atomicAdd(&stat_out[lane * 4 + j], red[lane * 4 + j]);
                atomicAdd(&stat_out[HID + lane * 4 + j], red[128 + lane * 4 + j]);
            }
        }
    }
}

// ================= launcher =================
extern "C" void kernel_launch(void* const* d_in, const int* in_sizes, int n_in,
                              void* d_out, int out_size) {
    const float* x = (const float*)d_in[0];
    const int* ei = (const int*)d_in[1];   // int32 (JAX default, x64 disabled)
    const float* ea = (const float*)d_in[2];
    const float* W1 = (const float*)d_in[3];
    const float* b1 = (const float*)d_in[4];
    const float* g1 = (const float*)d_in[5];
    const float* be1 = (const float*)d_in[6];
    const float* W2 = (const float*)d_in[7];
    const float* b2 = (const float*)d_in[8];
    const float* bn_g = (const float*)d_in[9];
    const float* bn_b = (const float*)d_in[10];

    int M = in_sizes[0] / HID;
    int E = in_sizes[2] / HID;
    float* out = (float*)d_out;

    void *agg_p, *zh_p, *xh_p, *t_p, *stats_p;
    cudaGetSymbolAddress(&agg_p, g_agg);
    cudaGetSymbolAddress(&zh_p, g_zh);
    cudaGetSymbolAddress(&xh_p, g_xh);
    cudaGetSymbolAddress(&t_p, g_t);
    cudaGetSymbolAddress(&stats_p, g_stats);
    float* stats = (float*)stats_p;

    cudaFuncSetAttribute(gemm_kernel<false, false, false, true, false>,
                         cudaFuncAttributeMaxDynamicSharedMemorySize, GEMM_SMEM);
    cudaFuncSetAttribute(gemm_kernel<true, true, true, true, true>,
                         cudaFuncAttributeMaxDynamicSharedMemorySize, GEMM_SMEM);
    cudaFuncSetAttribute(gemm_kernel<true, true, true, false, false>,
                         cudaFuncAttributeMaxDynamicSharedMemorySize, GEMM_SMEM);

    const int* srcI = ei;
    const int* dstI = ei + E;
    int eb = (E + 255) / 256;
    int gb = (M + 63) / 64;
    int ab = (M * 32 + 255) / 256;  // warp per node
    int xcb = (M * HID / 8 + 255) / 256;
    float invN = 1.0f / (float)M;

    // x -> fp16 + CSR build (scan zeroes stats/cnt/cur for graph replays)
    xconv_kernel<<<xcb, 256>>>(x, M * HID / 8);
    hist_kernel<<<eb, 256>>>(dstI, E);
    scan_kernel<<<1, 1024>>>(M, E);
    scatter_kernel<<<eb, 256>>>(dstI, E);

    for (int i = 0; i < 4; i++) {
        const __half* zsrc = (i == 0) ? (const __half*)xh_p : (const __half*)zh_p;
        float* stat_t = stats + (size_t)(2 * i) * 2 * HID;
        float* stat_z = stats + (size_t)(2 * i + 1) * 2 * HID;
        float* stat_z_prev = stats + (size_t)(2 * i - 1) * 2 * HID;

        // aggregate includes self/residual term: GEMM1 input fully formed here
        if (i == 0)
            agg_kernel<false><<<ab, 256>>>(zsrc, ea, srcI, nullptr, nullptr, nullptr,
                                           (float*)agg_p, M, invN);
        else
            agg_kernel<true><<<ab, 256>>>(zsrc, ea, srcI, stat_z_prev,
                                          bn_g + (size_t)(i - 1) * HID,
                                          bn_b + (size_t)(i - 1) * HID,
                                          (float*)agg_p, M, invN);

        // GEMM1: raw stage of agg (no transform), fp32 out t, stats
        gemm_kernel<false, false, false, true, false><<<gb, 256, GEMM_SMEM>>>(
            (const float*)agg_p, nullptr, nullptr, nullptr, invN,
            W1 + (size_t)i * HID * HID, b1 + (size_t)i * HID,
            (float*)t_p, nullptr, stat_t, M);

        // GEMM2: BN(t)+ReLU in, ReLU out
        if (i < 3)
            gemm_kernel<true, true, true, true, true><<<gb, 256, GEMM_SMEM>>>(
                (const float*)t_p, stat_t,
                g1 + (size_t)i * HID, be1 + (size_t)i * HID, invN,
                W2 + (size_t)i * HID * HID, b2 + (size_t)i * HID,
                nullptr, (__half*)zh_p, stat_z, M);
        else
            gemm_kernel<true, true, true, false, false><<<gb, 256, GEMM_SMEM>>>(
                (const float*)t_p, stat_t,
                g1 + (size_t)i * HID, be1 + (size_t)i * HID, invN,
                W2 + (size_t)i * HID * HID, b2 + (size_t)i * HID,
                out, nullptr, nullptr, M);
    }
}